// round 8
// baseline (speedup 1.0000x reference)
#include <cuda_runtime.h>
#include <cstdint>

#define ALPHA 26
#define TPB   128
#define NTOK  4
#define TOKT  (TPB * NTOK)              // 512 tokens per tile
#define TILE_FLOATS (TOKT * ALPHA)      // 13312
#define TILE_BYTES  (TILE_FLOATS * 4)   // 53248
#define SEQ   8192
#define GRID  296                       // 2 blocks/SM * 148 SMs

__device__ __forceinline__ uint32_t smem_u32(const void* p) {
    return (uint32_t)__cvta_generic_to_shared(p);
}
__device__ __forceinline__ void mbar_init(uint32_t mbar, uint32_t cnt) {
    asm volatile("mbarrier.init.shared.b64 [%0], %1;" :: "r"(mbar), "r"(cnt) : "memory");
}
__device__ __forceinline__ void mbar_expect_tx(uint32_t mbar, uint32_t bytes) {
    asm volatile("mbarrier.arrive.expect_tx.shared.b64 _, [%0], %1;"
                 :: "r"(mbar), "r"(bytes) : "memory");
}
__device__ __forceinline__ void mbar_wait(uint32_t mbar, uint32_t parity) {
    asm volatile(
        "{\n\t.reg .pred P;\n\t"
        "WAIT_%=:\n\t"
        "mbarrier.try_wait.parity.acquire.cta.shared::cta.b64 P, [%0], %1, 0x989680;\n\t"
        "@P bra.uni DONE_%=;\n\t"
        "bra.uni WAIT_%=;\n\t"
        "DONE_%=:\n\t}"
        :: "r"(mbar), "r"(parity) : "memory");
}
__device__ __forceinline__ void bulk_load(uint32_t sdst, const void* gsrc,
                                          uint32_t bytes, uint32_t mbar) {
    asm volatile(
        "cp.async.bulk.shared::cta.global.mbarrier::complete_tx::bytes [%0], [%1], %2, [%3];"
        :: "r"(sdst), "l"(gsrc), "r"(bytes), "r"(mbar) : "memory");
}
__device__ __forceinline__ void bulk_store(void* gdst, uint32_t ssrc, uint32_t bytes) {
    asm volatile("cp.async.bulk.global.shared::cta.bulk_group [%0], [%1], %2;"
                 :: "l"(gdst), "r"(ssrc), "r"(bytes) : "memory");
}
__device__ __forceinline__ void bulk_commit()   { asm volatile("cp.async.bulk.commit_group;" ::: "memory"); }
__device__ __forceinline__ void bulk_wait_read(){ asm volatile("cp.async.bulk.wait_group.read 0;" ::: "memory"); }
__device__ __forceinline__ void bulk_wait_all() { asm volatile("cp.async.bulk.wait_group 0;" ::: "memory"); }
__device__ __forceinline__ void fence_async()   { asm volatile("fence.proxy.async.shared::cta;" ::: "memory"); }

__global__ __launch_bounds__(TPB, 2)
void rotor_kernel(const float* __restrict__ x,
                  const float* __restrict__ rotor,
                  float* __restrict__ out, int nTiles)
{
    extern __shared__ __align__(128) float s_dyn[];     // 2 * TILE_FLOATS
    __shared__ __align__(16) float s_rn[ALPHA][ALPHA + 2];
    __shared__ float s_inv[ALPHA];
    __shared__ __align__(8) unsigned long long s_mbar[2];

    const int tid = threadIdx.x;

    // --- normalize rotor rows into smem (once per persistent block) ---
    if (tid < ALPHA) {
        float ss = 0.f;
        #pragma unroll
        for (int j = 0; j < ALPHA; ++j) {
            float v = rotor[tid * ALPHA + j];
            ss = fmaf(v, v, ss);
        }
        s_inv[tid] = rsqrtf(ss);
    }
    if (tid == 0) {
        mbar_init(smem_u32(&s_mbar[0]), 1);
        mbar_init(smem_u32(&s_mbar[1]), 1);
    }
    __syncthreads();
    for (int e = tid; e < ALPHA * ALPHA; e += TPB) {
        int r = e / ALPHA;
        s_rn[r][e - r * ALPHA] = rotor[e] * s_inv[r];
    }
    __syncthreads();   // rn + mbarrier init visible

    const uint32_t sb0 = smem_u32(s_dyn);
    const uint32_t mb0 = smem_u32(&s_mbar[0]);
    const uint32_t mb1 = smem_u32(&s_mbar[1]);

    // --- prologue: prefetch first two tiles ---
    if (tid == 0) {
        int t0 = blockIdx.x;
        if (t0 < nTiles) {
            mbar_expect_tx(mb0, TILE_BYTES);
            bulk_load(sb0, x + (size_t)t0 * TILE_FLOATS, TILE_BYTES, mb0);
        }
        if (t0 + GRID < nTiles) {
            mbar_expect_tx(mb1, TILE_BYTES);
            bulk_load(sb0 + TILE_BYTES, x + (size_t)(t0 + GRID) * TILE_FLOATS,
                      TILE_BYTES, mb1);
        }
    }

    int k = 0;
    for (int t = blockIdx.x; t < nTiles; t += GRID, ++k) {
        const int b  = k & 1;
        const int ph = (k >> 1) & 1;
        mbar_wait(b ? mb1 : mb0, ph);

        float* __restrict__ sb = s_dyn + b * TILE_FLOATS;

        // --- four tokens per thread ---
        int shift[NTOK];
        const float* __restrict__ xr[NTOK];
        #pragma unroll
        for (int q = 0; q < NTOK; ++q) {
            int tok = t * TOKT + tid + q * TPB;
            shift[q] = (tok & (SEQ - 1)) % ALPHA;
            xr[q] = sb + (tid + q * TPB) * ALPHA;
        }

        unsigned long long acc[NTOK][13];
        #pragma unroll
        for (int q = 0; q < NTOK; ++q)
            #pragma unroll
            for (int p = 0; p < 13; ++p) acc[q][p] = 0ull;

        #pragma unroll
        for (int r = 0; r < ALPHA; ++r) {
            // broadcast rn row r: 6 x LDS.128 + 1 x LDS.64 (warp-uniform)
            unsigned long long bb[13];
            const float4* __restrict__ rr4 = (const float4*)(&s_rn[r][0]);
            #pragma unroll
            for (int c = 0; c < 6; ++c) {
                float4 f = rr4[c];
                asm("mov.b64 %0, {%1, %2};" : "=l"(bb[2*c  ]) : "f"(f.x), "f"(f.y));
                asm("mov.b64 %0, {%1, %2};" : "=l"(bb[2*c+1]) : "f"(f.z), "f"(f.w));
            }
            {
                float2 f = *(const float2*)(&s_rn[r][24]);
                asm("mov.b64 %0, {%1, %2};" : "=l"(bb[12]) : "f"(f.x), "f"(f.y));
            }

            unsigned long long xx[NTOK];
            #pragma unroll
            for (int q = 0; q < NTOK; ++q) {
                int i = r - shift[q];
                i += (i >> 31) & ALPHA;              // branchless mod 26
                float xv = xr[q][i];
                asm("mov.b64 %0, {%1, %1};" : "=l"(xx[q]) : "f"(xv));
            }

            #pragma unroll
            for (int q = 0; q < NTOK; ++q)
                #pragma unroll
                for (int p = 0; p < 13; ++p)
                    asm("fma.rn.f32x2 %0, %1, %2, %0;"
                        : "+l"(acc[q][p]) : "l"(bb[p]), "l"(xx[q]));
        }

        // --- per-token softmax; write back into own region of sb ---
        #pragma unroll
        for (int q = 0; q < NTOK; ++q) {
            float v[ALPHA];
            #pragma unroll
            for (int p = 0; p < 13; ++p)
                asm("mov.b64 {%0, %1}, %2;"
                    : "=f"(v[2*p]), "=f"(v[2*p+1]) : "l"(acc[q][p]));

            float mx = v[0];
            #pragma unroll
            for (int j = 1; j < ALPHA; ++j) mx = fmaxf(mx, v[j]);
            float sum = 0.f;
            #pragma unroll
            for (int j = 0; j < ALPHA; ++j) {
                v[j] = __expf(v[j] - mx);
                sum += v[j];
            }
            const float inv = __fdividef(1.0f, sum);

            float2* w = (float2*)(sb + (tid + q * TPB) * ALPHA);   // 8B aligned
            #pragma unroll
            for (int p = 0; p < 13; ++p)
                w[p] = make_float2(v[2*p] * inv, v[2*p+1] * inv);
        }
        __syncthreads();                             // all STS done, all reads of sb done

        if (tid == 0) {
            fence_async();                           // STS visible to async proxy
            bulk_store(out + (size_t)t * TILE_FLOATS, sb0 + b * TILE_BYTES, TILE_BYTES);
            bulk_commit();
            const int tn = t + 2 * GRID;
            if (tn < nTiles) {
                bulk_wait_read();                    // store's smem reads drained
                mbar_expect_tx(b ? mb1 : mb0, TILE_BYTES);
                bulk_load(sb0 + b * TILE_BYTES, x + (size_t)tn * TILE_FLOATS,
                          TILE_BYTES, b ? mb1 : mb0);
            }
        }
        // other threads run ahead to next tile's mbar_wait (other buffer) — safe
    }

    if (tid == 0) bulk_wait_all();                   // stores complete before exit
}

extern "C" void kernel_launch(void* const* d_in, const int* in_sizes, int n_in,
                              void* d_out, int out_size)
{
    const float* x     = (const float*)d_in[0];   // [128, 8192, 26] f32
    const float* rotor = (const float*)d_in[1];   // [26, 26] f32
    float* out         = (float*)d_out;

    const int total_tokens = out_size / ALPHA;    // 1,048,576
    const int nTiles = total_tokens / TOKT;       // 2048

    const int dyn_smem = 2 * TILE_BYTES;          // 106496 B
    cudaFuncSetAttribute(rotor_kernel,
                         cudaFuncAttributeMaxDynamicSharedMemorySize, dyn_smem);

    rotor_kernel<<<GRID, TPB, dyn_smem>>>(x, rotor, out, nTiles);
}

// round 9
// speedup vs baseline: 1.3491x; 1.3491x over previous
#include <cuda_runtime.h>
#include <cstdint>

#define ALPHA 26
#define TPB   256
#define WARPS (TPB / 32)                 // 8 warps per block
#define CHUNK_TOK    64                  // tokens per warp-chunk (2 per lane)
#define CHUNK_FLOATS (CHUNK_TOK * ALPHA) // 1664
#define CHUNK_BYTES  (CHUNK_FLOATS * 4)  // 6656 (16B multiple)
#define SEQ   8192
#define GRID  296                        // 2 blocks/SM * 148 SMs
#define TW    (GRID * WARPS)             // 2368 warp pipelines

__device__ __forceinline__ uint32_t smem_u32(const void* p) {
    return (uint32_t)__cvta_generic_to_shared(p);
}
__device__ __forceinline__ void mbar_init(uint32_t mbar, uint32_t cnt) {
    asm volatile("mbarrier.init.shared.b64 [%0], %1;" :: "r"(mbar), "r"(cnt) : "memory");
}
__device__ __forceinline__ void mbar_expect_tx(uint32_t mbar, uint32_t bytes) {
    asm volatile("mbarrier.arrive.expect_tx.shared.b64 _, [%0], %1;"
                 :: "r"(mbar), "r"(bytes) : "memory");
}
__device__ __forceinline__ void mbar_wait(uint32_t mbar, uint32_t parity) {
    asm volatile(
        "{\n\t.reg .pred P;\n\t"
        "WAIT_%=:\n\t"
        "mbarrier.try_wait.parity.acquire.cta.shared::cta.b64 P, [%0], %1, 0x989680;\n\t"
        "@P bra.uni DONE_%=;\n\t"
        "bra.uni WAIT_%=;\n\t"
        "DONE_%=:\n\t}"
        :: "r"(mbar), "r"(parity) : "memory");
}
__device__ __forceinline__ void bulk_load(uint32_t sdst, const void* gsrc,
                                          uint32_t bytes, uint32_t mbar) {
    asm volatile(
        "cp.async.bulk.shared::cta.global.mbarrier::complete_tx::bytes [%0], [%1], %2, [%3];"
        :: "r"(sdst), "l"(gsrc), "r"(bytes), "r"(mbar) : "memory");
}
__device__ __forceinline__ void bulk_store(void* gdst, uint32_t ssrc, uint32_t bytes) {
    asm volatile("cp.async.bulk.global.shared::cta.bulk_group [%0], [%1], %2;"
                 :: "l"(gdst), "r"(ssrc), "r"(bytes) : "memory");
}
__device__ __forceinline__ void bulk_commit()    { asm volatile("cp.async.bulk.commit_group;" ::: "memory"); }
__device__ __forceinline__ void bulk_wait_read() { asm volatile("cp.async.bulk.wait_group.read 0;" ::: "memory"); }
__device__ __forceinline__ void bulk_wait_all()  { asm volatile("cp.async.bulk.wait_group 0;" ::: "memory"); }
__device__ __forceinline__ void fence_async()    { asm volatile("fence.proxy.async.shared::cta;" ::: "memory"); }

__global__ __launch_bounds__(TPB, 2)
void rotor_kernel(const float* __restrict__ x,
                  const float* __restrict__ rotor,
                  float* __restrict__ out, int nChunks)
{
    extern __shared__ __align__(128) float s_dyn[];   // WARPS * 2 * CHUNK_FLOATS
    __shared__ __align__(16) float s_rn[ALPHA][ALPHA + 2];
    __shared__ float s_inv[ALPHA];
    __shared__ __align__(8) unsigned long long s_mbar[WARPS * 2];

    const int tid  = threadIdx.x;
    const int wid  = tid >> 5;
    const int lane = tid & 31;

    // --- normalize rotor rows into smem (once per persistent block) ---
    if (tid < ALPHA) {
        float ss = 0.f;
        #pragma unroll
        for (int j = 0; j < ALPHA; ++j) {
            float v = rotor[tid * ALPHA + j];
            ss = fmaf(v, v, ss);
        }
        s_inv[tid] = rsqrtf(ss);
    }
    if (tid < WARPS * 2) mbar_init(smem_u32(&s_mbar[tid]), 1);
    __syncthreads();
    for (int e = tid; e < ALPHA * ALPHA; e += TPB) {
        int r = e / ALPHA;
        s_rn[r][e - r * ALPHA] = rotor[e] * s_inv[r];
    }
    __syncthreads();   // rn + mbarrier init visible to all warps

    // per-warp resources
    float* __restrict__ wbuf = s_dyn + wid * 2 * CHUNK_FLOATS;
    const uint32_t wb  = smem_u32(wbuf);
    const uint32_t mbA = smem_u32(&s_mbar[wid * 2 + 0]);
    const uint32_t mbB = smem_u32(&s_mbar[wid * 2 + 1]);

    const int c0 = blockIdx.x * WARPS + wid;   // this warp's first chunk

    // --- prologue: prefetch first two chunks (lane 0 only) ---
    if (lane == 0) {
        if (c0 < nChunks) {
            mbar_expect_tx(mbA, CHUNK_BYTES);
            bulk_load(wb, x + (size_t)c0 * CHUNK_FLOATS, CHUNK_BYTES, mbA);
        }
        if (c0 + TW < nChunks) {
            mbar_expect_tx(mbB, CHUNK_BYTES);
            bulk_load(wb + CHUNK_BYTES, x + (size_t)(c0 + TW) * CHUNK_FLOATS,
                      CHUNK_BYTES, mbB);
        }
    }

    int k = 0;
    for (int c = c0; c < nChunks; c += TW, ++k) {
        const int b  = k & 1;
        const int ph = (k >> 1) & 1;
        mbar_wait(b ? mbB : mbA, ph);

        float* __restrict__ sb = wbuf + b * CHUNK_FLOATS;

        // --- two tokens per lane ---
        const int tok0 = c * CHUNK_TOK + lane;
        const int tok1 = tok0 + 32;
        const int shift0 = (tok0 & (SEQ - 1)) % ALPHA;
        const int shift1 = (tok1 & (SEQ - 1)) % ALPHA;
        const float* __restrict__ xr0 = sb + lane * ALPHA;
        const float* __restrict__ xr1 = sb + (lane + 32) * ALPHA;

        unsigned long long acc0[13], acc1[13];
        #pragma unroll
        for (int p = 0; p < 13; ++p) { acc0[p] = 0ull; acc1[p] = 0ull; }

        #pragma unroll
        for (int r = 0; r < ALPHA; ++r) {
            int i0 = r - shift0; i0 += (i0 >> 31) & ALPHA;
            int i1 = r - shift1; i1 += (i1 >> 31) & ALPHA;
            float xv0 = xr0[i0];
            float xv1 = xr1[i1];
            unsigned long long xx0, xx1;
            asm("mov.b64 %0, {%1, %1};" : "=l"(xx0) : "f"(xv0));
            asm("mov.b64 %0, {%1, %1};" : "=l"(xx1) : "f"(xv1));

            const float4* __restrict__ rr4 = (const float4*)(&s_rn[r][0]);
            #pragma unroll
            for (int cc = 0; cc < 6; ++cc) {
                float4 f = rr4[cc];                    // uniform LDS.128 broadcast
                unsigned long long b01, b23;
                asm("mov.b64 %0, {%1, %2};" : "=l"(b01) : "f"(f.x), "f"(f.y));
                asm("mov.b64 %0, {%1, %2};" : "=l"(b23) : "f"(f.z), "f"(f.w));
                asm("fma.rn.f32x2 %0, %1, %2, %0;" : "+l"(acc0[2*cc  ]) : "l"(b01), "l"(xx0));
                asm("fma.rn.f32x2 %0, %1, %2, %0;" : "+l"(acc0[2*cc+1]) : "l"(b23), "l"(xx0));
                asm("fma.rn.f32x2 %0, %1, %2, %0;" : "+l"(acc1[2*cc  ]) : "l"(b01), "l"(xx1));
                asm("fma.rn.f32x2 %0, %1, %2, %0;" : "+l"(acc1[2*cc+1]) : "l"(b23), "l"(xx1));
            }
            {
                float2 f = *(const float2*)(&s_rn[r][24]);
                unsigned long long bb;
                asm("mov.b64 %0, {%1, %2};" : "=l"(bb) : "f"(f.x), "f"(f.y));
                asm("fma.rn.f32x2 %0, %1, %2, %0;" : "+l"(acc0[12]) : "l"(bb), "l"(xx0));
                asm("fma.rn.f32x2 %0, %1, %2, %0;" : "+l"(acc1[12]) : "l"(bb), "l"(xx1));
            }
        }

        // --- softmax per token; write back into own region of sb ---
        float v0[ALPHA], v1[ALPHA];
        #pragma unroll
        for (int p = 0; p < 13; ++p) {
            asm("mov.b64 {%0, %1}, %2;" : "=f"(v0[2*p]), "=f"(v0[2*p+1]) : "l"(acc0[p]));
            asm("mov.b64 {%0, %1}, %2;" : "=f"(v1[2*p]), "=f"(v1[2*p+1]) : "l"(acc1[p]));
        }
        float mx0 = v0[0], mx1 = v1[0];
        #pragma unroll
        for (int j = 1; j < ALPHA; ++j) { mx0 = fmaxf(mx0, v0[j]); mx1 = fmaxf(mx1, v1[j]); }
        float sm0 = 0.f, sm1 = 0.f;
        #pragma unroll
        for (int j = 0; j < ALPHA; ++j) {
            v0[j] = __expf(v0[j] - mx0); sm0 += v0[j];
            v1[j] = __expf(v1[j] - mx1); sm1 += v1[j];
        }
        const float in0 = __fdividef(1.0f, sm0);
        const float in1 = __fdividef(1.0f, sm1);

        float2* w0 = (float2*)(sb + lane * ALPHA);
        float2* w1 = (float2*)(sb + (lane + 32) * ALPHA);
        #pragma unroll
        for (int p = 0; p < 13; ++p) {
            w0[p] = make_float2(v0[2*p] * in0, v0[2*p+1] * in0);
            w1[p] = make_float2(v1[2*p] * in1, v1[2*p+1] * in1);
        }
        __syncwarp();                                // warp's STS all done

        if (lane == 0) {
            fence_async();                           // STS visible to async proxy
            bulk_store(out + (size_t)c * CHUNK_FLOATS, wb + b * CHUNK_BYTES, CHUNK_BYTES);
            bulk_commit();
            const int cn = c + 2 * TW;
            if (cn < nChunks) {
                bulk_wait_read();                    // this buffer's store reads drained
                mbar_expect_tx(b ? mbB : mbA, CHUNK_BYTES);
                bulk_load(wb + b * CHUNK_BYTES, x + (size_t)cn * CHUNK_FLOATS,
                          CHUNK_BYTES, b ? mbB : mbA);
            }
        }
        // lanes 1..31 run ahead to next chunk's mbar_wait (other buffer) — safe
    }

    if (lane == 0) bulk_wait_all();                  // gmem stores complete before exit
}

extern "C" void kernel_launch(void* const* d_in, const int* in_sizes, int n_in,
                              void* d_out, int out_size)
{
    const float* x     = (const float*)d_in[0];   // [128, 8192, 26] f32
    const float* rotor = (const float*)d_in[1];   // [26, 26] f32
    float* out         = (float*)d_out;

    const int total_tokens = out_size / ALPHA;    // 1,048,576
    const int nChunks = total_tokens / CHUNK_TOK; // 16384

    const int dyn_smem = WARPS * 2 * CHUNK_BYTES; // 106496 B
    cudaFuncSetAttribute(rotor_kernel,
                         cudaFuncAttributeMaxDynamicSharedMemorySize, dyn_smem);

    rotor_kernel<<<GRID, TPB, dyn_smem>>>(x, rotor, out, nChunks);
}